// round 14
// baseline (speedup 1.0000x reference)
#include <cuda_runtime.h>
#include <cuda_bf16.h>
#include <cstdint>

#define S_LEN 2048
#define DIMM  2048
#define NH    16
#define NKV   8
#define HD    128
#define NTOK  4096
#define QKV_OUT 4096

typedef unsigned int u32;
typedef unsigned long long u64;
typedef __nv_bfloat16 bf16;

// ---------------- PTX helpers ----------------
__device__ __forceinline__ u32 smem_u32(const void* p) {
    u32 a; asm("{ .reg .u64 t; cvta.to.shared.u64 t, %1; cvt.u32.u64 %0, t; }" : "=r"(a) : "l"(p));
    return a;
}
#define CP16(dst, src) asm volatile("cp.async.cg.shared.global [%0], [%1], 16;" :: "r"(dst), "l"(src))
#define CPC()  asm volatile("cp.async.commit_group;" ::: "memory")
#define CPW0() asm volatile("cp.async.wait_group 0;" ::: "memory")
#define CPW1() asm volatile("cp.async.wait_group 1;" ::: "memory")

__device__ __forceinline__ void ldsm4(u32 &r0, u32 &r1, u32 &r2, u32 &r3, u32 a) {
    asm volatile("ldmatrix.sync.aligned.m8n8.x4.shared.b16 {%0,%1,%2,%3}, [%4];"
        : "=r"(r0), "=r"(r1), "=r"(r2), "=r"(r3) : "r"(a));
}
__device__ __forceinline__ void ldsm4t(u32 &r0, u32 &r1, u32 &r2, u32 &r3, u32 a) {
    asm volatile("ldmatrix.sync.aligned.m8n8.x4.trans.shared.b16 {%0,%1,%2,%3}, [%4];"
        : "=r"(r0), "=r"(r1), "=r"(r2), "=r"(r3) : "r"(a));
}
__device__ __forceinline__ void mmabf(float* d, const u32* a, const u32* b) {
    asm volatile("mma.sync.aligned.m16n8k16.row.col.f32.bf16.bf16.f32 "
        "{%0,%1,%2,%3},{%4,%5,%6,%7},{%8,%9},{%0,%1,%2,%3};"
        : "+f"(d[0]), "+f"(d[1]), "+f"(d[2]), "+f"(d[3])
        : "r"(a[0]), "r"(a[1]), "r"(a[2]), "r"(a[3]), "r"(b[0]), "r"(b[1]));
}
// pack f0(lo half),f1(hi half) to bf16x2 hi; residual pack in lo
__device__ __forceinline__ u32 split2(float f0, float f1, u32 &lo) {
    u32 h; asm("cvt.rn.bf16x2.f32 %0, %1, %2;" : "=r"(h) : "f"(f1), "f"(f0));
    float h0 = __uint_as_float(h << 16);
    float h1 = __uint_as_float(h & 0xffff0000u);
    asm("cvt.rn.bf16x2.f32 %0, %1, %2;" : "=r"(lo) : "f"(f1 - h1), "f"(f0 - h0));
    return h;
}

// ---------------- scratch ----------------
__device__ bf16 g_xh[(size_t)NTOK * DIMM],     g_xl[(size_t)NTOK * DIMM];
__device__ bf16 g_wqh[(size_t)QKV_OUT * DIMM], g_wql[(size_t)QKV_OUT * DIMM];
__device__ bf16 g_woh[(size_t)DIMM * DIMM],    g_wol[(size_t)DIMM * DIMM];
__device__ bf16 g_qh[(size_t)NTOK * NH * HD],  g_ql[(size_t)NTOK * NH * HD];
__device__ bf16 g_kh[(size_t)NTOK * NKV * HD], g_kl[(size_t)NTOK * NKV * HD];
__device__ bf16 g_vh[(size_t)NTOK * NKV * HD], g_vl[(size_t)NTOK * NKV * HD];
__device__ bf16 g_ah[(size_t)NTOK * DIMM],     g_al[(size_t)NTOK * DIMM];

// ---------------- merged elementwise split (x, w_qkv, w_out in ONE launch) ----------------
#define N4_X  (NTOK * DIMM / 4)
#define N4_WQ (QKV_OUT * DIMM / 4)
#define N4_WO (DIMM * DIMM / 4)
__global__ __launch_bounds__(256) void split_all(
    const float4* __restrict__ x, const float4* __restrict__ wq, const float4* __restrict__ wo)
{
    int i = blockIdx.x * 256 + threadIdx.x;
    const float4* src; uint2 *hi, *lo; int j;
    if (i < N4_X) {
        j = i; src = x; hi = (uint2*)g_xh; lo = (uint2*)g_xl;
    } else if (i < N4_X + N4_WQ) {
        j = i - N4_X; src = wq; hi = (uint2*)g_wqh; lo = (uint2*)g_wql;
    } else if (i < N4_X + N4_WQ + N4_WO) {
        j = i - N4_X - N4_WQ; src = wo; hi = (uint2*)g_woh; lo = (uint2*)g_wol;
    } else return;
    float4 v = src[j];
    u32 l0, l1;
    u32 h0 = split2(v.x, v.y, l0);
    u32 h1 = split2(v.z, v.w, l1);
    hi[j] = make_uint2(h0, h1);
    lo[j] = make_uint2(l0, l1);
}

// ---------------- bf16x3 GEMM: C = A[M,K] * B[N,K]^T ----------------
// CTA 128x128, 8 warps (64x32), k32 stages, 2-stage double buffer.
#define GEMM_SMEM (2 * 32768)
template<int MODE>
__global__ __launch_bounds__(256, 2) void gemm_bf3(
    const bf16* __restrict__ Ah, const bf16* __restrict__ Al,
    const bf16* __restrict__ Bh, const bf16* __restrict__ Bl,
    float* __restrict__ C, int M, int N, int K,
    const float* __restrict__ freqs,
    const float* __restrict__ qw, const float* __restrict__ kw)
{
    extern __shared__ char gsm[];
    const u32 sb = smem_u32(gsm);
    const int tid = threadIdx.x, L = tid & 31, w = tid >> 5;
    const int m0 = blockIdx.y * 128, n0 = blockIdx.x * 128;
    const int mw = w & 1, nq = w >> 1;

    float acc[4][4][4];
    #pragma unroll
    for (int a = 0; a < 4; a++)
        #pragma unroll
        for (int b = 0; b < 4; b++)
            #pragma unroll
            for (int c = 0; c < 4; c++) acc[a][b][c] = 0.f;

    const int NS = K >> 5;

    #define GEMM_STAGE_CP(s) do { \
        int k0 = (s) * 32; \
        u32 bufb = sb + ((s) & 1) * 32768; \
        _Pragma("unroll") \
        for (int rr = 0; rr < 4; rr++) { \
            int id = tid + rr * 256; \
            int row = id >> 3, c = id & 7, pl = c >> 2, kc = c & 3; \
            const bf16* srcA = (pl ? Al : Ah) + (size_t)(m0 + row) * K + k0 + kc * 8; \
            CP16(bufb + row * 128 + (((u32)(c ^ (row & 7))) << 4), srcA); \
            const bf16* srcB = (pl ? Bl : Bh) + (size_t)(n0 + row) * K + k0 + kc * 8; \
            CP16(bufb + 16384 + row * 128 + (((u32)(c ^ (row & 7))) << 4), srcB); \
        } \
    } while (0)

    GEMM_STAGE_CP(0); CPC();

    for (int s = 0; s < NS; s++) {
        if (s + 1 < NS) { GEMM_STAGE_CP(s + 1); CPC(); CPW1(); }
        else CPW0();
        __syncthreads();
        u32 ab = sb + (s & 1) * 32768;
        u32 bb = ab + 16384;
        #pragma unroll
        for (int ks = 0; ks < 2; ks++) {
            u32 afh[4][4], afl[4][4], bh[4][2], bl[4][2];
            #pragma unroll
            for (int mt = 0; mt < 4; mt++) {
                int row = mw * 64 + mt * 16 + (L & 7) + ((L >> 3) & 1) * 8;
                int ch = ks * 2 + (L >> 4);
                u32 base = ab + row * 128;
                ldsm4(afh[mt][0], afh[mt][1], afh[mt][2], afh[mt][3],
                      base + ((u32)(ch ^ (row & 7)) << 4));
                ldsm4(afl[mt][0], afl[mt][1], afl[mt][2], afl[mt][3],
                      base + ((u32)((ch + 4) ^ (row & 7)) << 4));
            }
            #pragma unroll
            for (int p = 0; p < 2; p++) {
                int row = nq * 32 + p * 16 + (L & 7) + (L >> 4) * 8;
                int ch = ks * 2 + ((L >> 3) & 1);
                u32 base = bb + row * 128;
                u32 r0, r1, r2, r3;
                ldsm4(r0, r1, r2, r3, base + ((u32)(ch ^ (row & 7)) << 4));
                bh[2*p][0] = r0; bh[2*p][1] = r1; bh[2*p+1][0] = r2; bh[2*p+1][1] = r3;
                ldsm4(r0, r1, r2, r3, base + ((u32)((ch + 4) ^ (row & 7)) << 4));
                bl[2*p][0] = r0; bl[2*p][1] = r1; bl[2*p+1][0] = r2; bl[2*p+1][1] = r3;
            }
            // plane-major issue: consecutive HMMAs hit different accumulators
            #pragma unroll
            for (int mt = 0; mt < 4; mt++)
                #pragma unroll
                for (int nt = 0; nt < 4; nt++)
                    mmabf(acc[mt][nt], afh[mt], bh[nt]);
            #pragma unroll
            for (int mt = 0; mt < 4; mt++)
                #pragma unroll
                for (int nt = 0; nt < 4; nt++)
                    mmabf(acc[mt][nt], afh[mt], bl[nt]);
            #pragma unroll
            for (int mt = 0; mt < 4; mt++)
                #pragma unroll
                for (int nt = 0; nt < 4; nt++)
                    mmabf(acc[mt][nt], afl[mt], bh[nt]);
        }
        __syncthreads();
    }

    if (MODE == 0) {
        #pragma unroll
        for (int mt = 0; mt < 4; mt++) {
            int r0 = m0 + mw * 64 + mt * 16 + (L >> 2);
            #pragma unroll
            for (int nt = 0; nt < 4; nt++) {
                int c0 = n0 + nq * 32 + nt * 8 + (L & 3) * 2;
                *(float2*)(C + (size_t)r0 * N + c0)       = make_float2(acc[mt][nt][0], acc[mt][nt][1]);
                *(float2*)(C + (size_t)(r0 + 8) * N + c0) = make_float2(acc[mt][nt][2], acc[mt][nt][3]);
            }
        }
    } else {
        // -------- fused QKV epilogue (n-tile == one head) --------
        const int nb = blockIdx.x;   // 0..15 Q heads, 16..23 K heads, 24..31 V heads
        if (nb >= 24) {
            const int h = nb - 24;
            #pragma unroll
            for (int mt = 0; mt < 4; mt++) {
                int rowA = mw * 64 + mt * 16 + (L >> 2);
                int tA = m0 + rowA;
                #pragma unroll
                for (int nt = 0; nt < 4; nt++) {
                    int d = nq * 32 + nt * 8 + (L & 3) * 2;
                    size_t iA = ((size_t)tA * NKV + h) * HD + d;
                    size_t iB = ((size_t)(tA + 8) * NKV + h) * HD + d;
                    u32 lo_;
                    u32 hi_ = split2(acc[mt][nt][0], acc[mt][nt][1], lo_);
                    *(u32*)&g_vh[iA] = hi_; *(u32*)&g_vl[iA] = lo_;
                    hi_ = split2(acc[mt][nt][2], acc[mt][nt][3], lo_);
                    *(u32*)&g_vh[iB] = hi_; *(u32*)&g_vl[iB] = lo_;
                }
            }
        } else {
            __shared__ float ssred[128][5];
            __shared__ float ssfin[128];
            float pA[4], pB[4];
            #pragma unroll
            for (int mt = 0; mt < 4; mt++) {
                float sA = 0.f, sB = 0.f;
                #pragma unroll
                for (int nt = 0; nt < 4; nt++) {
                    sA += acc[mt][nt][0] * acc[mt][nt][0] + acc[mt][nt][1] * acc[mt][nt][1];
                    sB += acc[mt][nt][2] * acc[mt][nt][2] + acc[mt][nt][3] * acc[mt][nt][3];
                }
                pA[mt] = sA; pB[mt] = sB;
            }
            #pragma unroll
            for (int o = 1; o < 4; o <<= 1) {
                #pragma unroll
                for (int mt = 0; mt < 4; mt++) {
                    pA[mt] += __shfl_xor_sync(0xffffffffu, pA[mt], o);
                    pB[mt] += __shfl_xor_sync(0xffffffffu, pB[mt], o);
                }
            }
            __syncthreads();
            if ((L & 3) == 0) {
                #pragma unroll
                for (int mt = 0; mt < 4; mt++) {
                    int rowA = mw * 64 + mt * 16 + (L >> 2);
                    ssred[rowA][nq] = pA[mt];
                    ssred[rowA + 8][nq] = pB[mt];
                }
            }
            __syncthreads();
            if (tid < 128)
                ssfin[tid] = ssred[tid][0] + ssred[tid][1] + ssred[tid][2] + ssred[tid][3];
            __syncthreads();

            const bool isq = nb < 16;
            const int h = isq ? nb : nb - 16;
            const float* wv = isq ? qw : kw;
            #pragma unroll
            for (int mt = 0; mt < 4; mt++) {
                int rowA = mw * 64 + mt * 16 + (L >> 2);
                int tA = m0 + rowA, tB = tA + 8;
                float nfA = rsqrtf(ssfin[rowA]     * (1.0f / HD) + 1e-5f);
                float nfB = rsqrtf(ssfin[rowA + 8] * (1.0f / HD) + 1e-5f);
                int sA = tA & (S_LEN - 1), sB = tB & (S_LEN - 1);
                #pragma unroll
                for (int nt = 0; nt < 4; nt++) {
                    int d = nq * 32 + nt * 8 + (L & 3) * 2;
                    float2 wp = *(const float2*)(wv + d);
                    int f = d >> 1;
                    float4 fcA = *(const float4*)(freqs + ((size_t)sA * 64 + f) * 4);
                    float4 fcB = *(const float4*)(freqs + ((size_t)sB * 64 + f) * 4);
                    {
                        float x0 = acc[mt][nt][0] * nfA * wp.x;
                        float x1 = acc[mt][nt][1] * nfA * wp.y;
                        float o0 = fcA.x * x0 + fcA.y * x1;
                        float o1 = fcA.z * x0 + fcA.w * x1;
                        u32 lo_; u32 hi_ = split2(o0, o1, lo_);
                        if (isq) {
                            size_t i = ((size_t)tA * NH + h) * HD + d;
                            *(u32*)&g_qh[i] = hi_; *(u32*)&g_ql[i] = lo_;
                        } else {
                            size_t i = ((size_t)tA * NKV + h) * HD + d;
                            *(u32*)&g_kh[i] = hi_; *(u32*)&g_kl[i] = lo_;
                        }
                    }
                    {
                        float x0 = acc[mt][nt][2] * nfB * wp.x;
                        float x1 = acc[mt][nt][3] * nfB * wp.y;
                        float o0 = fcB.x * x0 + fcB.y * x1;
                        float o1 = fcB.z * x0 + fcB.w * x1;
                        u32 lo_; u32 hi_ = split2(o0, o1, lo_);
                        if (isq) {
                            size_t i = ((size_t)tB * NH + h) * HD + d;
                            *(u32*)&g_qh[i] = hi_; *(u32*)&g_ql[i] = lo_;
                        } else {
                            size_t i = ((size_t)tB * NKV + h) * HD + d;
                            *(u32*)&g_kh[i] = hi_; *(u32*)&g_kl[i] = lo_;
                        }
                    }
                }
            }
        }
    }
}

// ---------------- tensor-core flash attention (bf16x3), 2 CTAs/SM ----------------
// grid (S/64, NH, B), 128 threads (4 warps). smem: Q 32KB + 2 x (K 16KB + V 16KB) = 96KB.
// Q fragments hoisted into registers before the KV loop (loop-invariant).
#define FL_SMEM (32768 + 2 * 32768)
__global__ __launch_bounds__(128, 2) void flash_bf(const float* __restrict__ mask)
{
    extern __shared__ char fsm[];
    const u32 sb = smem_u32(fsm);
    const int tid = threadIdx.x, L = tid & 31, w = tid >> 5;
    const int h = blockIdx.y, b = blockIdx.z;
    const int hkv = h >> 1;
    const int q0 = blockIdx.x * 64;
    const int tok0 = b * S_LEN;
    const float scale = 0.088388347762f;

    // stage Q tile (64 rows x 512B)
    #pragma unroll
    for (int i = 0; i < 16; i++) {
        int id = tid + i * 128;
        int row = id >> 5, c = id & 31, pl = c >> 4, cc = c & 15;
        const bf16* src = (pl ? g_ql : g_qh)
            + ((size_t)(tok0 + q0 + row) * NH + h) * HD + cc * 8;
        CP16(sb + row * 512 + ((u32)(c ^ (row & 7)) << 4), src);
    }
    CPC();

    // KV tile: 32 keys. K 16KB @ +0, V 16KB @ +16384 within a 32KB slot.
    #define FL_KV_CP(tt) do { \
        u32 bufb = sb + 32768 + ((tt) & 1) * 32768; \
        int kt_ = (tt) * 32; \
        _Pragma("unroll") \
        for (int i = 0; i < 16; i++) { \
            int id = tid + i * 128; \
            int tensor = id >> 10; \
            int rem = id & 1023; \
            int row = rem >> 5, c = rem & 31, pl = c >> 4, cc = c & 15; \
            const bf16* src; \
            if (tensor == 0) src = (pl ? g_kl : g_kh) \
                + ((size_t)(tok0 + kt_ + row) * NKV + hkv) * HD + cc * 8; \
            else             src = (pl ? g_vl : g_vh) \
                + ((size_t)(tok0 + kt_ + row) * NKV + hkv) * HD + cc * 8; \
            CP16(bufb + tensor * 16384 + row * 512 + ((u32)(c ^ (row & 7)) << 4), src); \
        } \
    } while (0)

    FL_KV_CP(0); CPC();

    // wait for Q group (leave KV0 possibly pending), then hoist Q frags to registers
    CPW1();
    __syncthreads();
    u32 qfh[8][4], qfl[8][4];
    {
        int row = w * 16 + (L & 7) + ((L >> 3) & 1) * 8;
        u32 base = sb + row * 512;
        #pragma unroll
        for (int kd = 0; kd < 8; kd++) {
            int ch = kd * 2 + (L >> 4);
            ldsm4(qfh[kd][0], qfh[kd][1], qfh[kd][2], qfh[kd][3],
                  base + ((u32)(ch ^ (row & 7)) << 4));
            ldsm4(qfl[kd][0], qfl[kd][1], qfl[kd][2], qfl[kd][3],
                  base + ((u32)((ch + 16) ^ (row & 7)) << 4));
        }
    }

    float m0r = -1e30f, m1r = -1e30f, l0r = 0.f, l1r = 0.f;
    float acc[16][4];
    #pragma unroll
    for (int i = 0; i < 16; i++)
        #pragma unroll
        for (int j = 0; j < 4; j++) acc[i][j] = 0.f;

    const int g = L >> 2;
    const float* mp0 = mask + (size_t)b * S_LEN * S_LEN
                       + (size_t)(q0 + w * 16 + g) * S_LEN + (L & 3) * 2;

    for (int t = 0; t < 64; t++) {
        if (t + 1 < 64) { FL_KV_CP(t + 1); CPC(); CPW1(); }
        else CPW0();
        __syncthreads();
        u32 kb = sb + 32768 + (t & 1) * 32768;
        u32 vb = kb + 16384;
        const int kt = t * 32;

        // ---- S = Q K^T over 32 keys (4 key-frags), 3 planes ----
        float s[4][4];
        #pragma unroll
        for (int f = 0; f < 4; f++)
            #pragma unroll
            for (int j = 0; j < 4; j++) s[f][j] = 0.f;

        #pragma unroll
        for (int kd = 0; kd < 8; kd++) {
            u32 kh[4][2], kl[4][2];
            #pragma unroll
            for (int p = 0; p < 2; p++) {
                int row = p * 16 + (L & 7) + (L >> 4) * 8;
                int ch = kd * 2 + ((L >> 3) & 1);
                u32 base = kb + row * 512;
                u32 r0, r1, r2, r3;
                ldsm4(r0, r1, r2, r3, base + ((u32)(ch ^ (row & 7)) << 4));
                kh[2*p][0] = r0; kh[2*p][1] = r1; kh[2*p+1][0] = r2; kh[2*p+1][1] = r3;
                ldsm4(r0, r1, r2, r3, base + ((u32)((ch + 16) ^ (row & 7)) << 4));
                kl[2*p][0] = r0; kl[2*p][1] = r1; kl[2*p+1][0] = r2; kl[2*p+1][1] = r3;
            }
            #pragma unroll
            for (int f = 0; f < 4; f++) {
                mmabf(s[f], qfh[kd], kh[f]);
                mmabf(s[f], qfh[kd], kl[f]);
                mmabf(s[f], qfl[kd], kh[f]);
            }
        }

        // ---- scale + mask + online softmax ----
        float mx0 = -1e30f, mx1 = -1e30f;
        #pragma unroll
        for (int f = 0; f < 4; f++) {
            float2 mv0 = *(const float2*)(mp0 + kt + f * 8);
            float2 mv1 = *(const float2*)(mp0 + 8 * S_LEN + kt + f * 8);
            s[f][0] = s[f][0] * scale + mv0.x;
            s[f][1] = s[f][1] * scale + mv0.y;
            s[f][2] = s[f][2] * scale + mv1.x;
            s[f][3] = s[f][3] * scale + mv1.y;
            mx0 = fmaxf(mx0, fmaxf(s[f][0], s[f][1]));
            mx1 = fmaxf(mx1, fmaxf(s[f][2], s[f][3]));
        }
        mx0 = fmaxf(mx0, __shfl_xor_sync(0xffffffffu, mx0, 1));
        mx0 = fmaxf(mx0, __shfl_xor_sync(0xffffffffu, mx0, 2));
        mx1 = fmaxf(mx1, __shfl_xor_sync(0xffffffffu, mx1, 1));
        mx1 = fmaxf(mx1, __shfl_xor_sync(0xffffffffu, mx1, 2));
        float mn0 = fmaxf(m0r, mx0), mn1 = fmaxf(m1r, mx1);
        float a0 = __expf(m0r - mn0), a1 = __expf(m1r - mn1);
        m0r = mn0; m1r = mn1;
        float sum0 = 0.f, sum1 = 0.f;
        #pragma unroll
        for (int f = 0; f < 4; f++) {
            s[f][0] = __expf(s[f][0] - mn0); sum0 += s[f][0];
            s[f][1] = __expf(s[f][1] - mn0); sum0 += s[f][1];
            s[f][2] = __expf(s[f][2] - mn1); sum1 += s[f][2];
            s[f][3] = __expf(s[f][3] - mn1); sum1 += s[f][3];
        }
        sum0 += __shfl_xor_sync(0xffffffffu, sum0, 1);
        sum0 += __shfl_xor_sync(0xffffffffu, sum0, 2);
        sum1 += __shfl_xor_sync(0xffffffffu, sum1, 1);
        sum1 += __shfl_xor_sync(0xffffffffu, sum1, 2);
        l0r = l0r * a0 + sum0;
        l1r = l1r * a1 + sum1;

        // ---- P -> bf16 hi/lo A-fragments (2 key-groups of 16) ----
        u32 ph[2][4], pl[2][4];
        #pragma unroll
        for (int kg = 0; kg < 2; kg++) {
            ph[kg][0] = split2(s[2*kg][0],   s[2*kg][1],   pl[kg][0]);
            ph[kg][1] = split2(s[2*kg][2],   s[2*kg][3],   pl[kg][1]);
            ph[kg][2] = split2(s[2*kg+1][0], s[2*kg+1][1], pl[kg][2]);
            ph[kg][3] = split2(s[2*kg+1][2], s[2*kg+1][3], pl[kg][3]);
        }

        // ---- rescale acc ----
        #pragma unroll
        for (int df = 0; df < 16; df++) {
            acc[df][0] *= a0; acc[df][1] *= a0;
            acc[df][2] *= a1; acc[df][3] *= a1;
        }

        // ---- O += P V (3 planes) ----
        #pragma unroll
        for (int kg = 0; kg < 2; kg++) {
            #pragma unroll
            for (int dp = 0; dp < 8; dp++) {
                int row = kg * 16 + (L & 7) + ((L >> 3) & 1) * 8;
                int ch = dp * 2 + (L >> 4);
                u32 base = vb + row * 512;
                u32 vh0[2], vh1[2], vl0[2], vl1[2];
                {
                    u32 r0, r1, r2, r3;
                    ldsm4t(r0, r1, r2, r3, base + ((u32)(ch ^ (row & 7)) << 4));
                    vh0[0] = r0; vh0[1] = r1; vh1[0] = r2; vh1[1] = r3;
                    ldsm4t(r0, r1, r2, r3, base + ((u32)((ch + 16) ^ (row & 7)) << 4));
                    vl0[0] = r0; vl0[1] = r1; vl1[0] = r2; vl1[1] = r3;
                }
                mmabf(acc[2*dp],   ph[kg], vh0);
                mmabf(acc[2*dp],   ph[kg], vl0);
                mmabf(acc[2*dp],   pl[kg], vh0);
                mmabf(acc[2*dp+1], ph[kg], vh1);
                mmabf(acc[2*dp+1], ph[kg], vl1);
                mmabf(acc[2*dp+1], pl[kg], vh1);
            }
        }
        __syncthreads();
    }

    float inv0 = 1.0f / l0r, inv1 = 1.0f / l1r;
    int qrow = tok0 + q0 + w * 16 + g;
    #pragma unroll
    for (int df = 0; df < 16; df++) {
        int col = h * HD + df * 8 + (L & 3) * 2;
        u32 lo_;
        u32 hi_ = split2(acc[df][0] * inv0, acc[df][1] * inv0, lo_);
        *(u32*)&g_ah[(size_t)qrow * DIMM + col] = hi_;
        *(u32*)&g_al[(size_t)qrow * DIMM + col] = lo_;
        hi_ = split2(acc[df][2] * inv1, acc[df][3] * inv1, lo_);
        *(u32*)&g_ah[(size_t)(qrow + 8) * DIMM + col] = hi_;
        *(u32*)&g_al[(size_t)(qrow + 8) * DIMM + col] = lo_;
    }
}

// ---------------- launch ----------------
extern "C" void kernel_launch(void* const* d_in, const int* in_sizes, int n_in,
                              void* d_out, int out_size)
{
    const float* x     = (const float*)d_in[0];
    const float* mask  = (const float*)d_in[1];
    const float* freqs = (const float*)d_in[2];
    const float* w_qkv = (const float*)d_in[3];
    const float* w_out = (const float*)d_in[4];
    const float* q_w   = (const float*)d_in[5];
    const float* k_w   = (const float*)d_in[6];
    float* out = (float*)d_out;

    bf16 *xh, *xl, *wqh, *wql, *woh, *wol, *ah, *al;
    cudaGetSymbolAddress((void**)&xh,  g_xh);  cudaGetSymbolAddress((void**)&xl,  g_xl);
    cudaGetSymbolAddress((void**)&wqh, g_wqh); cudaGetSymbolAddress((void**)&wql, g_wql);
    cudaGetSymbolAddress((void**)&woh, g_woh); cudaGetSymbolAddress((void**)&wol, g_wol);
    cudaGetSymbolAddress((void**)&ah,  g_ah);  cudaGetSymbolAddress((void**)&al,  g_al);

    cudaFuncSetAttribute(gemm_bf3<0>, cudaFuncAttributeMaxDynamicSharedMemorySize, GEMM_SMEM);
    cudaFuncSetAttribute(gemm_bf3<1>, cudaFuncAttributeMaxDynamicSharedMemorySize, GEMM_SMEM);
    cudaFuncSetAttribute(flash_bf,    cudaFuncAttributeMaxDynamicSharedMemorySize, FL_SMEM);

    // one launch for all three fp32 -> bf16 hi/lo splits
    split_all<<<(N4_X + N4_WQ + N4_WO + 255)/256, 256>>>(
        (const float4*)x, (const float4*)w_qkv, (const float4*)w_out);

    // QKV projection with fused RMSNorm+RoPE+split epilogue
    gemm_bf3<1><<<dim3(QKV_OUT/128, NTOK/128), 256, GEMM_SMEM>>>(
        xh, xl, wqh, wql, nullptr, NTOK, QKV_OUT, DIMM, freqs, q_w, k_w);

    // flash attention: 2 CTAs/SM (64-row Q tiles, 32-key KV tiles), Q frags in registers
    flash_bf<<<dim3(S_LEN/64, NH, 2), 128, FL_SMEM>>>(mask);

    // out projection
    gemm_bf3<0><<<dim3(DIMM/128, NTOK/128), 256, GEMM_SMEM>>>(
        ah, al, woh, wol, out, NTOK, DIMM, DIMM, nullptr, nullptr, nullptr);
}

// round 15
// speedup vs baseline: 1.0072x; 1.0072x over previous
#include <cuda_runtime.h>
#include <cuda_bf16.h>
#include <cstdint>

#define S_LEN 2048
#define DIMM  2048
#define NH    16
#define NKV   8
#define HD    128
#define NTOK  4096
#define QKV_OUT 4096

typedef unsigned int u32;
typedef unsigned long long u64;
typedef __nv_bfloat16 bf16;

// ---------------- PTX helpers ----------------
__device__ __forceinline__ u32 smem_u32(const void* p) {
    u32 a; asm("{ .reg .u64 t; cvta.to.shared.u64 t, %1; cvt.u32.u64 %0, t; }" : "=r"(a) : "l"(p));
    return a;
}
#define CP16(dst, src) asm volatile("cp.async.cg.shared.global [%0], [%1], 16;" :: "r"(dst), "l"(src))
#define CPC()  asm volatile("cp.async.commit_group;" ::: "memory")
#define CPW0() asm volatile("cp.async.wait_group 0;" ::: "memory")
#define CPW1() asm volatile("cp.async.wait_group 1;" ::: "memory")

__device__ __forceinline__ void ldsm4(u32 &r0, u32 &r1, u32 &r2, u32 &r3, u32 a) {
    asm volatile("ldmatrix.sync.aligned.m8n8.x4.shared.b16 {%0,%1,%2,%3}, [%4];"
        : "=r"(r0), "=r"(r1), "=r"(r2), "=r"(r3) : "r"(a));
}
__device__ __forceinline__ void ldsm4t(u32 &r0, u32 &r1, u32 &r2, u32 &r3, u32 a) {
    asm volatile("ldmatrix.sync.aligned.m8n8.x4.trans.shared.b16 {%0,%1,%2,%3}, [%4];"
        : "=r"(r0), "=r"(r1), "=r"(r2), "=r"(r3) : "r"(a));
}
__device__ __forceinline__ void mmabf(float* d, const u32* a, const u32* b) {
    asm volatile("mma.sync.aligned.m16n8k16.row.col.f32.bf16.bf16.f32 "
        "{%0,%1,%2,%3},{%4,%5,%6,%7},{%8,%9},{%0,%1,%2,%3};"
        : "+f"(d[0]), "+f"(d[1]), "+f"(d[2]), "+f"(d[3])
        : "r"(a[0]), "r"(a[1]), "r"(a[2]), "r"(a[3]), "r"(b[0]), "r"(b[1]));
}
// pack f0(lo half),f1(hi half) to bf16x2 hi; residual pack in lo
__device__ __forceinline__ u32 split2(float f0, float f1, u32 &lo) {
    u32 h; asm("cvt.rn.bf16x2.f32 %0, %1, %2;" : "=r"(h) : "f"(f1), "f"(f0));
    float h0 = __uint_as_float(h << 16);
    float h1 = __uint_as_float(h & 0xffff0000u);
    asm("cvt.rn.bf16x2.f32 %0, %1, %2;" : "=r"(lo) : "f"(f1 - h1), "f"(f0 - h0));
    return h;
}

// ---------------- scratch ----------------
__device__ bf16 g_xh[(size_t)NTOK * DIMM],     g_xl[(size_t)NTOK * DIMM];
__device__ bf16 g_wqh[(size_t)QKV_OUT * DIMM], g_wql[(size_t)QKV_OUT * DIMM];
__device__ bf16 g_woh[(size_t)DIMM * DIMM],    g_wol[(size_t)DIMM * DIMM];
__device__ bf16 g_qh[(size_t)NTOK * NH * HD],  g_ql[(size_t)NTOK * NH * HD];
__device__ bf16 g_kh[(size_t)NTOK * NKV * HD], g_kl[(size_t)NTOK * NKV * HD];
__device__ bf16 g_vh[(size_t)NTOK * NKV * HD], g_vl[(size_t)NTOK * NKV * HD];
__device__ bf16 g_ah[(size_t)NTOK * DIMM],     g_al[(size_t)NTOK * DIMM];

// ---------------- merged elementwise split (x, w_qkv, w_out in ONE launch) ----------------
#define N4_X  (NTOK * DIMM / 4)
#define N4_WQ (QKV_OUT * DIMM / 4)
#define N4_WO (DIMM * DIMM / 4)
__global__ __launch_bounds__(256) void split_all(
    const float4* __restrict__ x, const float4* __restrict__ wq, const float4* __restrict__ wo)
{
    int i = blockIdx.x * 256 + threadIdx.x;
    const float4* src; uint2 *hi, *lo; int j;
    if (i < N4_X) {
        j = i; src = x; hi = (uint2*)g_xh; lo = (uint2*)g_xl;
    } else if (i < N4_X + N4_WQ) {
        j = i - N4_X; src = wq; hi = (uint2*)g_wqh; lo = (uint2*)g_wql;
    } else if (i < N4_X + N4_WQ + N4_WO) {
        j = i - N4_X - N4_WQ; src = wo; hi = (uint2*)g_woh; lo = (uint2*)g_wol;
    } else return;
    float4 v = src[j];
    u32 l0, l1;
    u32 h0 = split2(v.x, v.y, l0);
    u32 h1 = split2(v.z, v.w, l1);
    hi[j] = make_uint2(h0, h1);
    lo[j] = make_uint2(l0, l1);
}

// ---------------- bf16x3 GEMM: C = A[M,K] * B[N,K]^T ----------------
// CTA 128x128, 8 warps (64x32), k32 stages, 2-stage double buffer.
#define GEMM_SMEM (2 * 32768)
template<int MODE>
__global__ __launch_bounds__(256, 2) void gemm_bf3(
    const bf16* __restrict__ Ah, const bf16* __restrict__ Al,
    const bf16* __restrict__ Bh, const bf16* __restrict__ Bl,
    float* __restrict__ C, int M, int N, int K,
    const float* __restrict__ freqs,
    const float* __restrict__ qw, const float* __restrict__ kw)
{
    extern __shared__ char gsm[];
    const u32 sb = smem_u32(gsm);
    const int tid = threadIdx.x, L = tid & 31, w = tid >> 5;
    const int m0 = blockIdx.y * 128, n0 = blockIdx.x * 128;
    const int mw = w & 1, nq = w >> 1;

    float acc[4][4][4];
    #pragma unroll
    for (int a = 0; a < 4; a++)
        #pragma unroll
        for (int b = 0; b < 4; b++)
            #pragma unroll
            for (int c = 0; c < 4; c++) acc[a][b][c] = 0.f;

    const int NS = K >> 5;

    #define GEMM_STAGE_CP(s) do { \
        int k0 = (s) * 32; \
        u32 bufb = sb + ((s) & 1) * 32768; \
        _Pragma("unroll") \
        for (int rr = 0; rr < 4; rr++) { \
            int id = tid + rr * 256; \
            int row = id >> 3, c = id & 7, pl = c >> 2, kc = c & 3; \
            const bf16* srcA = (pl ? Al : Ah) + (size_t)(m0 + row) * K + k0 + kc * 8; \
            CP16(bufb + row * 128 + (((u32)(c ^ (row & 7))) << 4), srcA); \
            const bf16* srcB = (pl ? Bl : Bh) + (size_t)(n0 + row) * K + k0 + kc * 8; \
            CP16(bufb + 16384 + row * 128 + (((u32)(c ^ (row & 7))) << 4), srcB); \
        } \
    } while (0)

    GEMM_STAGE_CP(0); CPC();

    for (int s = 0; s < NS; s++) {
        if (s + 1 < NS) { GEMM_STAGE_CP(s + 1); CPC(); CPW1(); }
        else CPW0();
        __syncthreads();
        u32 ab = sb + (s & 1) * 32768;
        u32 bb = ab + 16384;
        #pragma unroll
        for (int ks = 0; ks < 2; ks++) {
            u32 afh[4][4], afl[4][4], bh[4][2], bl[4][2];
            #pragma unroll
            for (int mt = 0; mt < 4; mt++) {
                int row = mw * 64 + mt * 16 + (L & 7) + ((L >> 3) & 1) * 8;
                int ch = ks * 2 + (L >> 4);
                u32 base = ab + row * 128;
                ldsm4(afh[mt][0], afh[mt][1], afh[mt][2], afh[mt][3],
                      base + ((u32)(ch ^ (row & 7)) << 4));
                ldsm4(afl[mt][0], afl[mt][1], afl[mt][2], afl[mt][3],
                      base + ((u32)((ch + 4) ^ (row & 7)) << 4));
            }
            #pragma unroll
            for (int p = 0; p < 2; p++) {
                int row = nq * 32 + p * 16 + (L & 7) + (L >> 4) * 8;
                int ch = ks * 2 + ((L >> 3) & 1);
                u32 base = bb + row * 128;
                u32 r0, r1, r2, r3;
                ldsm4(r0, r1, r2, r3, base + ((u32)(ch ^ (row & 7)) << 4));
                bh[2*p][0] = r0; bh[2*p][1] = r1; bh[2*p+1][0] = r2; bh[2*p+1][1] = r3;
                ldsm4(r0, r1, r2, r3, base + ((u32)((ch + 4) ^ (row & 7)) << 4));
                bl[2*p][0] = r0; bl[2*p][1] = r1; bl[2*p+1][0] = r2; bl[2*p+1][1] = r3;
            }
            // plane-major issue: consecutive HMMAs hit different accumulators
            #pragma unroll
            for (int mt = 0; mt < 4; mt++)
                #pragma unroll
                for (int nt = 0; nt < 4; nt++)
                    mmabf(acc[mt][nt], afh[mt], bh[nt]);
            #pragma unroll
            for (int mt = 0; mt < 4; mt++)
                #pragma unroll
                for (int nt = 0; nt < 4; nt++)
                    mmabf(acc[mt][nt], afh[mt], bl[nt]);
            #pragma unroll
            for (int mt = 0; mt < 4; mt++)
                #pragma unroll
                for (int nt = 0; nt < 4; nt++)
                    mmabf(acc[mt][nt], afl[mt], bh[nt]);
        }
        __syncthreads();
    }

    if (MODE == 0) {
        #pragma unroll
        for (int mt = 0; mt < 4; mt++) {
            int r0 = m0 + mw * 64 + mt * 16 + (L >> 2);
            #pragma unroll
            for (int nt = 0; nt < 4; nt++) {
                int c0 = n0 + nq * 32 + nt * 8 + (L & 3) * 2;
                *(float2*)(C + (size_t)r0 * N + c0)       = make_float2(acc[mt][nt][0], acc[mt][nt][1]);
                *(float2*)(C + (size_t)(r0 + 8) * N + c0) = make_float2(acc[mt][nt][2], acc[mt][nt][3]);
            }
        }
    } else {
        // -------- fused QKV epilogue (n-tile == one head) --------
        const int nb = blockIdx.x;   // 0..15 Q heads, 16..23 K heads, 24..31 V heads
        if (nb >= 24) {
            const int h = nb - 24;
            #pragma unroll
            for (int mt = 0; mt < 4; mt++) {
                int rowA = mw * 64 + mt * 16 + (L >> 2);
                int tA = m0 + rowA;
                #pragma unroll
                for (int nt = 0; nt < 4; nt++) {
                    int d = nq * 32 + nt * 8 + (L & 3) * 2;
                    size_t iA = ((size_t)tA * NKV + h) * HD + d;
                    size_t iB = ((size_t)(tA + 8) * NKV + h) * HD + d;
                    u32 lo_;
                    u32 hi_ = split2(acc[mt][nt][0], acc[mt][nt][1], lo_);
                    *(u32*)&g_vh[iA] = hi_; *(u32*)&g_vl[iA] = lo_;
                    hi_ = split2(acc[mt][nt][2], acc[mt][nt][3], lo_);
                    *(u32*)&g_vh[iB] = hi_; *(u32*)&g_vl[iB] = lo_;
                }
            }
        } else {
            __shared__ float ssred[128][5];
            __shared__ float ssfin[128];
            float pA[4], pB[4];
            #pragma unroll
            for (int mt = 0; mt < 4; mt++) {
                float sA = 0.f, sB = 0.f;
                #pragma unroll
                for (int nt = 0; nt < 4; nt++) {
                    sA += acc[mt][nt][0] * acc[mt][nt][0] + acc[mt][nt][1] * acc[mt][nt][1];
                    sB += acc[mt][nt][2] * acc[mt][nt][2] + acc[mt][nt][3] * acc[mt][nt][3];
                }
                pA[mt] = sA; pB[mt] = sB;
            }
            #pragma unroll
            for (int o = 1; o < 4; o <<= 1) {
                #pragma unroll
                for (int mt = 0; mt < 4; mt++) {
                    pA[mt] += __shfl_xor_sync(0xffffffffu, pA[mt], o);
                    pB[mt] += __shfl_xor_sync(0xffffffffu, pB[mt], o);
                }
            }
            __syncthreads();
            if ((L & 3) == 0) {
                #pragma unroll
                for (int mt = 0; mt < 4; mt++) {
                    int rowA = mw * 64 + mt * 16 + (L >> 2);
                    ssred[rowA][nq] = pA[mt];
                    ssred[rowA + 8][nq] = pB[mt];
                }
            }
            __syncthreads();
            if (tid < 128)
                ssfin[tid] = ssred[tid][0] + ssred[tid][1] + ssred[tid][2] + ssred[tid][3];
            __syncthreads();

            const bool isq = nb < 16;
            const int h = isq ? nb : nb - 16;
            const float* wv = isq ? qw : kw;
            #pragma unroll
            for (int mt = 0; mt < 4; mt++) {
                int rowA = mw * 64 + mt * 16 + (L >> 2);
                int tA = m0 + rowA, tB = tA + 8;
                float nfA = rsqrtf(ssfin[rowA]     * (1.0f / HD) + 1e-5f);
                float nfB = rsqrtf(ssfin[rowA + 8] * (1.0f / HD) + 1e-5f);
                int sA = tA & (S_LEN - 1), sB = tB & (S_LEN - 1);
                #pragma unroll
                for (int nt = 0; nt < 4; nt++) {
                    int d = nq * 32 + nt * 8 + (L & 3) * 2;
                    float2 wp = *(const float2*)(wv + d);
                    int f = d >> 1;
                    float4 fcA = *(const float4*)(freqs + ((size_t)sA * 64 + f) * 4);
                    float4 fcB = *(const float4*)(freqs + ((size_t)sB * 64 + f) * 4);
                    {
                        float x0 = acc[mt][nt][0] * nfA * wp.x;
                        float x1 = acc[mt][nt][1] * nfA * wp.y;
                        float o0 = fcA.x * x0 + fcA.y * x1;
                        float o1 = fcA.z * x0 + fcA.w * x1;
                        u32 lo_; u32 hi_ = split2(o0, o1, lo_);
                        if (isq) {
                            size_t i = ((size_t)tA * NH + h) * HD + d;
                            *(u32*)&g_qh[i] = hi_; *(u32*)&g_ql[i] = lo_;
                        } else {
                            size_t i = ((size_t)tA * NKV + h) * HD + d;
                            *(u32*)&g_kh[i] = hi_; *(u32*)&g_kl[i] = lo_;
                        }
                    }
                    {
                        float x0 = acc[mt][nt][2] * nfB * wp.x;
                        float x1 = acc[mt][nt][3] * nfB * wp.y;
                        float o0 = fcB.x * x0 + fcB.y * x1;
                        float o1 = fcB.z * x0 + fcB.w * x1;
                        u32 lo_; u32 hi_ = split2(o0, o1, lo_);
                        if (isq) {
                            size_t i = ((size_t)tB * NH + h) * HD + d;
                            *(u32*)&g_qh[i] = hi_; *(u32*)&g_ql[i] = lo_;
                        } else {
                            size_t i = ((size_t)tB * NKV + h) * HD + d;
                            *(u32*)&g_kh[i] = hi_; *(u32*)&g_kl[i] = lo_;
                        }
                    }
                }
            }
        }
    }
}

// ---------------- tensor-core flash attention (bf16x3), 2 CTAs/SM ----------------
// grid (S/64, NH, B), 128 threads (4 warps). smem: Q 32KB + 2 x (K 16KB + V 16KB) = 96KB.
// Dependency-breaking MMA issue order (plane-major QK, interleaved PV).
#define FL_SMEM (32768 + 2 * 32768)
__global__ __launch_bounds__(128, 2) void flash_bf(const float* __restrict__ mask)
{
    extern __shared__ char fsm[];
    const u32 sb = smem_u32(fsm);
    const int tid = threadIdx.x, L = tid & 31, w = tid >> 5;
    const int h = blockIdx.y, b = blockIdx.z;
    const int hkv = h >> 1;
    const int q0 = blockIdx.x * 64;
    const int tok0 = b * S_LEN;
    const float scale = 0.088388347762f;

    // stage Q tile (64 rows x 512B)
    #pragma unroll
    for (int i = 0; i < 16; i++) {
        int id = tid + i * 128;
        int row = id >> 5, c = id & 31, pl = c >> 4, cc = c & 15;
        const bf16* src = (pl ? g_ql : g_qh)
            + ((size_t)(tok0 + q0 + row) * NH + h) * HD + cc * 8;
        CP16(sb + row * 512 + ((u32)(c ^ (row & 7)) << 4), src);
    }
    CPC();

    // KV tile: 32 keys. K 16KB @ +0, V 16KB @ +16384 within a 32KB slot.
    #define FL_KV_CP(tt) do { \
        u32 bufb = sb + 32768 + ((tt) & 1) * 32768; \
        int kt_ = (tt) * 32; \
        _Pragma("unroll") \
        for (int i = 0; i < 16; i++) { \
            int id = tid + i * 128; \
            int tensor = id >> 10; \
            int rem = id & 1023; \
            int row = rem >> 5, c = rem & 31, pl = c >> 4, cc = c & 15; \
            const bf16* src; \
            if (tensor == 0) src = (pl ? g_kl : g_kh) \
                + ((size_t)(tok0 + kt_ + row) * NKV + hkv) * HD + cc * 8; \
            else             src = (pl ? g_vl : g_vh) \
                + ((size_t)(tok0 + kt_ + row) * NKV + hkv) * HD + cc * 8; \
            CP16(bufb + tensor * 16384 + row * 512 + ((u32)(c ^ (row & 7)) << 4), src); \
        } \
    } while (0)

    FL_KV_CP(0); CPC();

    float m0r = -1e30f, m1r = -1e30f, l0r = 0.f, l1r = 0.f;
    float acc[16][4];
    #pragma unroll
    for (int i = 0; i < 16; i++)
        #pragma unroll
        for (int j = 0; j < 4; j++) acc[i][j] = 0.f;

    const int g = L >> 2;
    const float* mp0 = mask + (size_t)b * S_LEN * S_LEN
                       + (size_t)(q0 + w * 16 + g) * S_LEN + (L & 3) * 2;

    for (int t = 0; t < 64; t++) {
        if (t + 1 < 64) { FL_KV_CP(t + 1); CPC(); CPW1(); }
        else CPW0();
        __syncthreads();
        u32 kb = sb + 32768 + (t & 1) * 32768;
        u32 vb = kb + 16384;
        const int kt = t * 32;

        // ---- S = Q K^T over 32 keys (4 key-frags), 3 planes ----
        float s[4][4];
        #pragma unroll
        for (int f = 0; f < 4; f++)
            #pragma unroll
            for (int j = 0; j < 4; j++) s[f][j] = 0.f;

        #pragma unroll
        for (int kd = 0; kd < 8; kd++) {
            u32 qh[4], ql[4];
            {
                int row = w * 16 + (L & 7) + ((L >> 3) & 1) * 8;
                int ch = kd * 2 + (L >> 4);
                u32 base = sb + row * 512;
                ldsm4(qh[0], qh[1], qh[2], qh[3], base + ((u32)(ch ^ (row & 7)) << 4));
                ldsm4(ql[0], ql[1], ql[2], ql[3], base + ((u32)((ch + 16) ^ (row & 7)) << 4));
            }
            u32 kh[4][2], kl[4][2];
            #pragma unroll
            for (int p = 0; p < 2; p++) {
                int row = p * 16 + (L & 7) + (L >> 4) * 8;
                int ch = kd * 2 + ((L >> 3) & 1);
                u32 base = kb + row * 512;
                u32 r0, r1, r2, r3;
                ldsm4(r0, r1, r2, r3, base + ((u32)(ch ^ (row & 7)) << 4));
                kh[2*p][0] = r0; kh[2*p][1] = r1; kh[2*p+1][0] = r2; kh[2*p+1][1] = r3;
                ldsm4(r0, r1, r2, r3, base + ((u32)((ch + 16) ^ (row & 7)) << 4));
                kl[2*p][0] = r0; kl[2*p][1] = r1; kl[2*p+1][0] = r2; kl[2*p+1][1] = r3;
            }
            // plane-major: consecutive HMMAs hit different accumulators s[f]
            #pragma unroll
            for (int f = 0; f < 4; f++) mmabf(s[f], qh, kh[f]);
            #pragma unroll
            for (int f = 0; f < 4; f++) mmabf(s[f], qh, kl[f]);
            #pragma unroll
            for (int f = 0; f < 4; f++) mmabf(s[f], ql, kh[f]);
        }

        // ---- scale + mask + online softmax ----
        float mx0 = -1e30f, mx1 = -1e30f;
        #pragma unroll
        for (int f = 0; f < 4; f++) {
            float2 mv0 = *(const float2*)(mp0 + kt + f * 8);
            float2 mv1 = *(const float2*)(mp0 + 8 * S_LEN + kt + f * 8);
            s[f][0] = s[f][0] * scale + mv0.x;
            s[f][1] = s[f][1] * scale + mv0.y;
            s[f][2] = s[f][2] * scale + mv1.x;
            s[f][3] = s[f][3] * scale + mv1.y;
            mx0 = fmaxf(mx0, fmaxf(s[f][0], s[f][1]));
            mx1 = fmaxf(mx1, fmaxf(s[f][2], s[f][3]));
        }
        mx0 = fmaxf(mx0, __shfl_xor_sync(0xffffffffu, mx0, 1));
        mx0 = fmaxf(mx0, __shfl_xor_sync(0xffffffffu, mx0, 2));
        mx1 = fmaxf(mx1, __shfl_xor_sync(0xffffffffu, mx1, 1));
        mx1 = fmaxf(mx1, __shfl_xor_sync(0xffffffffu, mx1, 2));
        float mn0 = fmaxf(m0r, mx0), mn1 = fmaxf(m1r, mx1);
        float a0 = __expf(m0r - mn0), a1 = __expf(m1r - mn1);
        m0r = mn0; m1r = mn1;
        float sum0 = 0.f, sum1 = 0.f;
        #pragma unroll
        for (int f = 0; f < 4; f++) {
            s[f][0] = __expf(s[f][0] - mn0); sum0 += s[f][0];
            s[f][1] = __expf(s[f][1] - mn0); sum0 += s[f][1];
            s[f][2] = __expf(s[f][2] - mn1); sum1 += s[f][2];
            s[f][3] = __expf(s[f][3] - mn1); sum1 += s[f][3];
        }
        sum0 += __shfl_xor_sync(0xffffffffu, sum0, 1);
        sum0 += __shfl_xor_sync(0xffffffffu, sum0, 2);
        sum1 += __shfl_xor_sync(0xffffffffu, sum1, 1);
        sum1 += __shfl_xor_sync(0xffffffffu, sum1, 2);
        l0r = l0r * a0 + sum0;
        l1r = l1r * a1 + sum1;

        // ---- P -> bf16 hi/lo A-fragments (2 key-groups of 16) ----
        u32 ph[2][4], pl[2][4];
        #pragma unroll
        for (int kg = 0; kg < 2; kg++) {
            ph[kg][0] = split2(s[2*kg][0],   s[2*kg][1],   pl[kg][0]);
            ph[kg][1] = split2(s[2*kg][2],   s[2*kg][3],   pl[kg][1]);
            ph[kg][2] = split2(s[2*kg+1][0], s[2*kg+1][1], pl[kg][2]);
            ph[kg][3] = split2(s[2*kg+1][2], s[2*kg+1][3], pl[kg][3]);
        }

        // ---- rescale acc ----
        #pragma unroll
        for (int df = 0; df < 16; df++) {
            acc[df][0] *= a0; acc[df][1] *= a0;
            acc[df][2] *= a1; acc[df][3] *= a1;
        }

        // ---- O += P V (3 planes), interleaved accumulators ----
        #pragma unroll
        for (int kg = 0; kg < 2; kg++) {
            #pragma unroll
            for (int dp = 0; dp < 8; dp++) {
                int row = kg * 16 + (L & 7) + ((L >> 3) & 1) * 8;
                int ch = dp * 2 + (L >> 4);
                u32 base = vb + row * 512;
                u32 vh0[2], vh1[2], vl0[2], vl1[2];
                {
                    u32 r0, r1, r2, r3;
                    ldsm4t(r0, r1, r2, r3, base + ((u32)(ch ^ (row & 7)) << 4));
                    vh0[0] = r0; vh0[1] = r1; vh1[0] = r2; vh1[1] = r3;
                    ldsm4t(r0, r1, r2, r3, base + ((u32)((ch + 16) ^ (row & 7)) << 4));
                    vl0[0] = r0; vl0[1] = r1; vl1[0] = r2; vl1[1] = r3;
                }
                mmabf(acc[2*dp],   ph[kg], vh0);
                mmabf(acc[2*dp+1], ph[kg], vh1);
                mmabf(acc[2*dp],   ph[kg], vl0);
                mmabf(acc[2*dp+1], ph[kg], vl1);
                mmabf(acc[2*dp],   pl[kg], vh0);
                mmabf(acc[2*dp+1], pl[kg], vh1);
            }
        }
        __syncthreads();
    }

    float inv0 = 1.0f / l0r, inv1 = 1.0f / l1r;
    int qrow = tok0 + q0 + w * 16 + g;
    #pragma unroll
    for (int df = 0; df < 16; df++) {
        int col = h * HD + df * 8 + (L & 3) * 2;
        u32 lo_;
        u32 hi_ = split2(acc[df][0] * inv0, acc[df][1] * inv0, lo_);
        *(u32*)&g_ah[(size_t)qrow * DIMM + col] = hi_;
        *(u32*)&g_al[(size_t)qrow * DIMM + col] = lo_;
        hi_ = split2(acc[df][2] * inv1, acc[df][3] * inv1, lo_);
        *(u32*)&g_ah[(size_t)(qrow + 8) * DIMM + col] = hi_;
        *(u32*)&g_al[(size_t)(qrow + 8) * DIMM + col] = lo_;
    }
}

// ---------------- launch ----------------
extern "C" void kernel_launch(void* const* d_in, const int* in_sizes, int n_in,
                              void* d_out, int out_size)
{
    const float* x     = (const float*)d_in[0];
    const float* mask  = (const float*)d_in[1];
    const float* freqs = (const float*)d_in[2];
    const float* w_qkv = (const float*)d_in[3];
    const float* w_out = (const float*)d_in[4];
    const float* q_w   = (const float*)d_in[5];
    const float* k_w   = (const float*)d_in[6];
    float* out = (float*)d_out;

    bf16 *xh, *xl, *wqh, *wql, *woh, *wol, *ah, *al;
    cudaGetSymbolAddress((void**)&xh,  g_xh);  cudaGetSymbolAddress((void**)&xl,  g_xl);
    cudaGetSymbolAddress((void**)&wqh, g_wqh); cudaGetSymbolAddress((void**)&wql, g_wql);
    cudaGetSymbolAddress((void**)&woh, g_woh); cudaGetSymbolAddress((void**)&wol, g_wol);
    cudaGetSymbolAddress((void**)&ah,  g_ah);  cudaGetSymbolAddress((void**)&al,  g_al);

    cudaFuncSetAttribute(gemm_bf3<0>, cudaFuncAttributeMaxDynamicSharedMemorySize, GEMM_SMEM);
    cudaFuncSetAttribute(gemm_bf3<1>, cudaFuncAttributeMaxDynamicSharedMemorySize, GEMM_SMEM);
    cudaFuncSetAttribute(flash_bf,    cudaFuncAttributeMaxDynamicSharedMemorySize, FL_SMEM);

    // one launch for all three fp32 -> bf16 hi/lo splits
    split_all<<<(N4_X + N4_WQ + N4_WO + 255)/256, 256>>>(
        (const float4*)x, (const float4*)w_qkv, (const float4*)w_out);

    // QKV projection with fused RMSNorm+RoPE+split epilogue
    gemm_bf3<1><<<dim3(QKV_OUT/128, NTOK/128), 256, GEMM_SMEM>>>(
        xh, xl, wqh, wql, nullptr, NTOK, QKV_OUT, DIMM, freqs, q_w, k_w);

    // flash attention: 2 CTAs/SM (64-row Q tiles, 32-key KV tiles)
    flash_bf<<<dim3(S_LEN/64, NH, 2), 128, FL_SMEM>>>(mask);

    // out projection
    gemm_bf3<0><<<dim3(DIMM/128, NTOK/128), 256, GEMM_SMEM>>>(
        ah, al, woh, wol, out, NTOK, DIMM, DIMM, nullptr, nullptr, nullptr);
}